// round 8
// baseline (speedup 1.0000x reference)
#include <cuda_runtime.h>
#include <cstdint>

#define NNODES 50000
#define NEDGES 800000

// ---------------- scratch (device globals; no allocation allowed) ----------
__device__ float g_fs[NNODES * 128];
__device__ float g_fd[NNODES * 128];
__device__ float g_h [NNODES * 128];
__device__ int   g_hist[NNODES];
__device__ int   g_rowptr[NNODES + 1];
__device__ int   g_woff[NNODES];
__device__ int   g_ssrc[NEDGES];

__device__ __forceinline__ float lrelu(float x) { return x > 0.f ? x : 0.2f * x; }

// ---- packed f32x2 helpers (FFMA2 path — not reachable from plain C++) -----
__device__ __forceinline__ unsigned long long pack2(float lo, float hi) {
    unsigned long long r;
    asm("mov.b64 %0, {%1, %2};" : "=l"(r) : "f"(lo), "f"(hi));
    return r;
}
__device__ __forceinline__ void unpack2(unsigned long long v, float& lo, float& hi) {
    asm("mov.b64 {%0, %1}, %2;" : "=f"(lo), "=f"(hi) : "l"(v));
}
__device__ __forceinline__ unsigned long long fma2(unsigned long long a,
                                                   unsigned long long b,
                                                   unsigned long long c) {
    unsigned long long d;
    asm("fma.rn.f32x2 %0, %1, %2, %3;" : "=l"(d) : "l"(a), "l"(b), "l"(c));
    return d;
}

// ================= CSR construction (once per launch, reused 3x) ============
__global__ void hist_count4(const int* __restrict__ dst, int* hist, int E4) {
    int i = blockIdx.x * blockDim.x + threadIdx.x;
    if (i < E4) {
        int4 d = reinterpret_cast<const int4*>(dst)[i];
        atomicAdd(&hist[d.x], 1);
        atomicAdd(&hist[d.y], 1);
        atomicAdd(&hist[d.z], 1);
        atomicAdd(&hist[d.w], 1);
    }
}
__global__ void scan_hist(const int* __restrict__ hist, int* rowptr, int* woff, int n) {
    __shared__ int sums[1024];
    const int t = threadIdx.x;
    const int chunk = (n + 1023) / 1024;
    const int begin = t * chunk;
    const int end   = min(begin + chunk, n);
    int s = 0;
    for (int i = begin; i < end; i++) s += hist[i];
    sums[t] = s;
    __syncthreads();
    for (int d = 1; d < 1024; d <<= 1) {
        int v = (t >= d) ? sums[t - d] : 0;
        __syncthreads();
        sums[t] += v;
        __syncthreads();
    }
    int off = sums[t] - s;   // exclusive prefix
    for (int i = begin; i < end; i++) {
        rowptr[i] = off;
        woff[i]   = off;
        off += hist[i];
    }
    if (end == n && begin <= n) rowptr[n] = off;
}
__global__ void edge_bucket4(const int* __restrict__ src, const int* __restrict__ dst,
                             int* woff, int* ssrc, int E4) {
    int i = blockIdx.x * blockDim.x + threadIdx.x;
    if (i < E4) {
        int4 d = reinterpret_cast<const int4*>(dst)[i];
        int4 s = reinterpret_cast<const int4*>(src)[i];
        int p0 = atomicAdd(&woff[d.x], 1);
        int p1 = atomicAdd(&woff[d.y], 1);
        int p2 = atomicAdd(&woff[d.z], 1);
        int p3 = atomicAdd(&woff[d.w], 1);
        ssrc[p0] = s.x;
        ssrc[p1] = s.y;
        ssrc[p2] = s.z;
        ssrc[p3] = s.w;
    }
}

// ---------------- dual GEMM (FFMA2): C0 = act(A)@W0+b0 ; C1 = act(A)@W1+b1 --
// Accumulators paired along M: acc2[i][j] holds rows (2i, 2i+1), col j.
template<int BN, int TM, int TN, int MAXB>
__global__ void __launch_bounds__(256, MAXB)
gemm_dual_k128(const float* __restrict__ A,
               const float* __restrict__ W0, const float* __restrict__ b0,
               const float* __restrict__ W1, const float* __restrict__ b1,
               float* __restrict__ C0, float* __restrict__ C1,
               int N, int relu_in)
{
    constexpr int K = 128, KC = 32;
    constexpr int TCOLS = (2 * BN) / TN;
    constexpr int TROWS = 256 / TCOLS;
    constexpr int BM = TROWS * TM;
    static_assert(TM % 4 == 0 && TN % 4 == 0, "vectorized tiling");

    __shared__ __align__(16) float As[KC][BM + 4];
    __shared__ __align__(16) float Wsm[KC][2 * BN];

    const int t  = threadIdx.x;
    const int tx = t % TCOLS;
    const int ty = t / TCOLS;
    const int rowBase = blockIdx.x * BM;

    unsigned long long acc2[TM / 2][TN];
    #pragma unroll
    for (int i = 0; i < TM / 2; i++)
        #pragma unroll
        for (int j = 0; j < TN; j++) acc2[i][j] = 0ull;

    for (int kc = 0; kc < K; kc += KC) {
        #pragma unroll
        for (int i = 0; i < (BM * KC) / (256 * 4); ++i) {
            int fi = t + i * 256;
            int r  = fi / (KC / 4);
            int c4 = fi % (KC / 4);
            int gr = rowBase + r;
            float4 v = make_float4(0.f, 0.f, 0.f, 0.f);
            if (gr < N) {
                v = reinterpret_cast<const float4*>(A + (size_t)gr * K + kc)[c4];
                if (relu_in) {
                    v.x = fmaxf(v.x, 0.f); v.y = fmaxf(v.y, 0.f);
                    v.z = fmaxf(v.z, 0.f); v.w = fmaxf(v.w, 0.f);
                }
            }
            As[c4 * 4 + 0][r] = v.x;
            As[c4 * 4 + 1][r] = v.y;
            As[c4 * 4 + 2][r] = v.z;
            As[c4 * 4 + 3][r] = v.w;
        }
        #pragma unroll
        for (int i = 0; i < (KC * 2 * BN) / (256 * 4); ++i) {
            int fi = t + i * 256;
            int r  = fi / ((2 * BN) / 4);
            int c4 = fi % ((2 * BN) / 4);
            int col = c4 * 4;
            float4 v;
            if (col < BN) v = reinterpret_cast<const float4*>(W0 + (size_t)(kc + r) * BN + col)[0];
            else          v = reinterpret_cast<const float4*>(W1 + (size_t)(kc + r) * BN + (col - BN))[0];
            reinterpret_cast<float4*>(&Wsm[r][0])[c4] = v;
        }
        __syncthreads();

        #pragma unroll
        for (int k = 0; k < KC; k++) {
            // A pairs come out of shared pre-packed (two adjacent M rows)
            unsigned long long ap[TM / 2];
            #pragma unroll
            for (int i = 0; i < TM / 4; i++) {
                ulonglong2 q = *reinterpret_cast<const ulonglong2*>(&As[k][ty * TM + i * 4]);
                ap[i * 2 + 0] = q.x;
                ap[i * 2 + 1] = q.y;
            }
            unsigned long long wd[TN];
            #pragma unroll
            for (int j = 0; j < TN / 4; j++) {
                float4 w = *reinterpret_cast<const float4*>(&Wsm[k][tx * TN + j * 4]);
                wd[j * 4 + 0] = pack2(w.x, w.x);
                wd[j * 4 + 1] = pack2(w.y, w.y);
                wd[j * 4 + 2] = pack2(w.z, w.z);
                wd[j * 4 + 3] = pack2(w.w, w.w);
            }
            #pragma unroll
            for (int i = 0; i < TM / 2; i++)
                #pragma unroll
                for (int j = 0; j < TN; j++)
                    acc2[i][j] = fma2(ap[i], wd[j], acc2[i][j]);
        }
        __syncthreads();
    }

    const int half = (tx * TN) / BN;
    const int col  = (tx * TN) % BN;
    float*       C  = half ? C1 : C0;
    const float* bb = half ? b1 : b0;
    float bias[TN];
    #pragma unroll
    for (int j = 0; j < TN; j++) bias[j] = bb[col + j];

    #pragma unroll
    for (int i = 0; i < TM / 2; i++) {
        float lo[TN], hi[TN];
        #pragma unroll
        for (int j = 0; j < TN; j++) unpack2(acc2[i][j], lo[j], hi[j]);
        int gr0 = rowBase + ty * TM + 2 * i;
        int gr1 = gr0 + 1;
        if (gr0 < N) {
            #pragma unroll
            for (int j = 0; j < TN / 4; j++) {
                float4 o = make_float4(lo[j*4+0] + bias[j*4+0], lo[j*4+1] + bias[j*4+1],
                                       lo[j*4+2] + bias[j*4+2], lo[j*4+3] + bias[j*4+3]);
                *reinterpret_cast<float4*>(C + (size_t)gr0 * BN + col + j * 4) = o;
            }
        }
        if (gr1 < N) {
            #pragma unroll
            for (int j = 0; j < TN / 4; j++) {
                float4 o = make_float4(hi[j*4+0] + bias[j*4+0], hi[j*4+1] + bias[j*4+1],
                                       hi[j*4+2] + bias[j*4+2], hi[j*4+3] + bias[j*4+3]);
                *reinterpret_cast<float4*>(C + (size_t)gr1 * BN + col + j * 4) = o;
            }
        }
    }
}

// ========== CSR edge aggregation, H=4: warp per dst, 2 edges in flight ======
__global__ void edge_csr4(const int* __restrict__ rowptr, const int* __restrict__ ssrc,
                          const float* __restrict__ fs, const float* __restrict__ fd,
                          const float* __restrict__ a, float* __restrict__ out, int N)
{
    const int lane = threadIdx.x & 31;
    const int d    = (blockIdx.x * blockDim.x + threadIdx.x) >> 5;
    if (d >= N) return;

    const float4* fs4 = reinterpret_cast<const float4*>(fs);
    float4 v  = reinterpret_cast<const float4*>(fd)[(size_t)d * 32 + lane];
    float4 av = reinterpret_cast<const float4*>(a)[lane];

    float4 acc = make_float4(0.f, 0.f, 0.f, 0.f);
    float den = 0.f;

    const int start = rowptr[d];
    const int end   = rowptr[d + 1];
    if (start < end) {
        const int last = end - 1;
        // prefetch first pair (clamped indices; invalid slots masked at exp)
        float4 ua = fs4[(size_t)__ldg(ssrc + start) * 32 + lane];
        float4 ub = fs4[(size_t)__ldg(ssrc + min(start + 1, last)) * 32 + lane];
        for (int i = start; i < end; i += 2) {
            float4 u0 = ua, u1 = ub;
            // prefetch next pair
            ua = fs4[(size_t)__ldg(ssrc + min(i + 2, last)) * 32 + lane];
            ub = fs4[(size_t)__ldg(ssrc + min(i + 3, last)) * 32 + lane];

            float p0 = lrelu(u0.x + v.x) * av.x + lrelu(u0.y + v.y) * av.y
                     + lrelu(u0.z + v.z) * av.z + lrelu(u0.w + v.w) * av.w;
            float p1 = lrelu(u1.x + v.x) * av.x + lrelu(u1.y + v.y) * av.y
                     + lrelu(u1.z + v.z) * av.z + lrelu(u1.w + v.w) * av.w;
            p0 += __shfl_xor_sync(0xffffffffu, p0, 1);
            p1 += __shfl_xor_sync(0xffffffffu, p1, 1);
            p0 += __shfl_xor_sync(0xffffffffu, p0, 2);
            p1 += __shfl_xor_sync(0xffffffffu, p1, 2);
            p0 += __shfl_xor_sync(0xffffffffu, p0, 4);
            p1 += __shfl_xor_sync(0xffffffffu, p1, 4);
            float ex0 = __expf(p0);                       // shift-invariant softmax
            float ex1 = (i + 1 < end) ? __expf(p1) : 0.f; // mask phantom edge
            acc.x = fmaf(u0.x, ex0, acc.x);
            acc.y = fmaf(u0.y, ex0, acc.y);
            acc.z = fmaf(u0.z, ex0, acc.z);
            acc.w = fmaf(u0.w, ex0, acc.w);
            acc.x = fmaf(u1.x, ex1, acc.x);
            acc.y = fmaf(u1.y, ex1, acc.y);
            acc.z = fmaf(u1.z, ex1, acc.z);
            acc.w = fmaf(u1.w, ex1, acc.w);
            den += ex0 + ex1;
        }
    }
    float sc = (den > 0.f) ? 1.0f / den : 0.f;   // zero-degree -> zeros
    acc.x *= sc; acc.y *= sc; acc.z *= sc; acc.w *= sc;
    reinterpret_cast<float4*>(out)[(size_t)d * 32 + lane] = acc;
}

// ========== CSR edge aggregation, H=1 (32 feats): warp=dst, 4 edge slots ====
__global__ void edge_csr1(const int* __restrict__ rowptr, const int* __restrict__ ssrc,
                          const float* __restrict__ fs, const float* __restrict__ fd,
                          const float* __restrict__ a, float* __restrict__ out, int N)
{
    const int lane = threadIdx.x & 31;
    const int d    = (blockIdx.x * blockDim.x + threadIdx.x) >> 5;
    if (d >= N) return;
    const int slot = lane >> 3;
    const int sub  = lane & 7;

    const float4* fs4 = reinterpret_cast<const float4*>(fs);
    float4 v  = reinterpret_cast<const float4*>(fd)[(size_t)d * 8 + sub];
    float4 av = reinterpret_cast<const float4*>(a)[sub];

    float4 acc = make_float4(0.f, 0.f, 0.f, 0.f);
    float den = 0.f;

    const int start = rowptr[d];
    const int end   = rowptr[d + 1];
    const int iters = (end - start + 3) >> 2;

    int idx0 = start + slot;
    float4 un = make_float4(0.f, 0.f, 0.f, 0.f);
    if (idx0 < end) un = fs4[(size_t)__ldg(ssrc + idx0) * 8 + sub];

    for (int it = 0; it < iters; it++) {
        bool ok = (start + it * 4 + slot) < end;
        float4 u = un;
        int nidx = start + (it + 1) * 4 + slot;
        if (nidx < end) un = fs4[(size_t)__ldg(ssrc + nidx) * 8 + sub];
        else            un = make_float4(0.f, 0.f, 0.f, 0.f);

        float p = lrelu(u.x + v.x) * av.x + lrelu(u.y + v.y) * av.y
                + lrelu(u.z + v.z) * av.z + lrelu(u.w + v.w) * av.w;
        p += __shfl_xor_sync(0xffffffffu, p, 1);
        p += __shfl_xor_sync(0xffffffffu, p, 2);
        p += __shfl_xor_sync(0xffffffffu, p, 4);
        float ex = ok ? __expf(p) : 0.f;
        acc.x = fmaf(u.x, ex, acc.x);
        acc.y = fmaf(u.y, ex, acc.y);
        acc.z = fmaf(u.z, ex, acc.z);
        acc.w = fmaf(u.w, ex, acc.w);
        den += ex;
    }
    #pragma unroll
    for (int m = 8; m <= 16; m <<= 1) {
        acc.x += __shfl_xor_sync(0xffffffffu, acc.x, m);
        acc.y += __shfl_xor_sync(0xffffffffu, acc.y, m);
        acc.z += __shfl_xor_sync(0xffffffffu, acc.z, m);
        acc.w += __shfl_xor_sync(0xffffffffu, acc.w, m);
        den   += __shfl_xor_sync(0xffffffffu, den,   m);
    }
    if (slot == 0) {
        float sc = (den > 0.f) ? 1.0f / den : 0.f;
        acc.x *= sc; acc.y *= sc; acc.z *= sc; acc.w *= sc;
        reinterpret_cast<float4*>(out)[(size_t)d * 8 + sub] = acc;
    }
}

// ---------------- launch -----------------------------------------------------
extern "C" void kernel_launch(void* const* d_in, const int* in_sizes, int n_in,
                              void* d_out, int out_size)
{
    const float* feat = (const float*)d_in[0];
    const int*   src  = (const int*)d_in[1];
    const int*   dst  = (const int*)d_in[2];
    const float* Ws0 = (const float*)d_in[3];  const float* bs0 = (const float*)d_in[4];
    const float* Wd0 = (const float*)d_in[5];  const float* bd0 = (const float*)d_in[6];
    const float* a0  = (const float*)d_in[7];
    const float* Ws1 = (const float*)d_in[8];  const float* bs1 = (const float*)d_in[9];
    const float* Wd1 = (const float*)d_in[10]; const float* bd1 = (const float*)d_in[11];
    const float* a1  = (const float*)d_in[12];
    const float* Ws2 = (const float*)d_in[13]; const float* bs2 = (const float*)d_in[14];
    const float* Wd2 = (const float*)d_in[15]; const float* bd2 = (const float*)d_in[16];
    const float* a2  = (const float*)d_in[17];
    float* out = (float*)d_out;

    const int N = in_sizes[0] / 128;
    const int E = in_sizes[1];

    float *fs, *fd, *h;
    int *hist, *rowptr, *woff, *ssrc;
    cudaGetSymbolAddress((void**)&fs,     g_fs);
    cudaGetSymbolAddress((void**)&fd,     g_fd);
    cudaGetSymbolAddress((void**)&h,      g_h);
    cudaGetSymbolAddress((void**)&hist,   g_hist);
    cudaGetSymbolAddress((void**)&rowptr, g_rowptr);
    cudaGetSymbolAddress((void**)&woff,   g_woff);
    cudaGetSymbolAddress((void**)&ssrc,   g_ssrc);

    const int gemmGridBig   = (N + 63) / 64;   // BM=64 (TM=8, TN=8)
    const int gemmGridSmall = (N + 63) / 64;   // BM=64 (TM=4, TN=4)
    const int edgeGrid = (N * 32 + 255) / 256; // one warp per dst
    const int E4 = E / 4;
    const int eg4 = (E4 + 255) / 256;

    // ---- CSR build (src/dst constant across layers; reused 3x) ----
    cudaMemsetAsync(hist, 0, (size_t)N * sizeof(int));
    hist_count4<<<eg4, 256>>>(dst, hist, E4);
    scan_hist<<<1, 1024>>>(hist, rowptr, woff, N);
    edge_bucket4<<<eg4, 256>>>(src, dst, woff, ssrc, E4);

    // ---- layer 0 (input 128 -> 4x32) ----
    gemm_dual_k128<128, 8, 8, 2><<<gemmGridBig, 256>>>(feat, Ws0, bs0, Wd0, bd0, fs, fd, N, 0);
    edge_csr4<<<edgeGrid, 256>>>(rowptr, ssrc, fs, fd, a0, h, N);

    // ---- layer 1 (ReLU(h) 128 -> 4x32) ----
    gemm_dual_k128<128, 8, 8, 2><<<gemmGridBig, 256>>>(h, Ws1, bs1, Wd1, bd1, fs, fd, N, 1);
    edge_csr4<<<edgeGrid, 256>>>(rowptr, ssrc, fs, fd, a1, h, N);

    // ---- layer 2 (ReLU(h) 128 -> 1x32), mean over 1 head == identity ----
    gemm_dual_k128<32, 4, 4, 2><<<gemmGridSmall, 256>>>(h, Ws2, bs2, Wd2, bd2, fs, fd, N, 1);
    edge_csr1<<<edgeGrid, 256>>>(rowptr, ssrc, fs, fd, a2, out, N);
}

// round 9
// speedup vs baseline: 1.0538x; 1.0538x over previous
#include <cuda_runtime.h>
#include <cstdint>

#define NNODES 50000
#define NEDGES 800000

// ---------------- scratch (device globals; no allocation allowed) ----------
__device__ float g_fs[NNODES * 128];
__device__ float g_fd[NNODES * 128];
__device__ float g_h [NNODES * 128];
__device__ int   g_hist[NNODES];
__device__ int   g_rowptr[NNODES + 1];
__device__ int   g_woff[NNODES];
__device__ int   g_ssrc[NEDGES];

__device__ __forceinline__ float lrelu(float x) { return x > 0.f ? x : 0.2f * x; }

// ---- packed f32x2 helpers (FFMA2 path — not reachable from plain C++) -----
__device__ __forceinline__ unsigned long long pack2(float lo, float hi) {
    unsigned long long r;
    asm("mov.b64 %0, {%1, %2};" : "=l"(r) : "f"(lo), "f"(hi));
    return r;
}
__device__ __forceinline__ void unpack2(unsigned long long v, float& lo, float& hi) {
    asm("mov.b64 {%0, %1}, %2;" : "=f"(lo), "=f"(hi) : "l"(v));
}
__device__ __forceinline__ unsigned long long fma2(unsigned long long a,
                                                   unsigned long long b,
                                                   unsigned long long c) {
    unsigned long long d;
    asm("fma.rn.f32x2 %0, %1, %2, %3;" : "=l"(d) : "l"(a), "l"(b), "l"(c));
    return d;
}

// ================= CSR construction (once per launch, reused 3x) ============
__global__ void hist_count4(const int* __restrict__ dst, int* hist, int E4) {
    int i = blockIdx.x * blockDim.x + threadIdx.x;
    if (i < E4) {
        int4 d = reinterpret_cast<const int4*>(dst)[i];
        atomicAdd(&hist[d.x], 1);
        atomicAdd(&hist[d.y], 1);
        atomicAdd(&hist[d.z], 1);
        atomicAdd(&hist[d.w], 1);
    }
}
__global__ void scan_hist(const int* __restrict__ hist, int* rowptr, int* woff, int n) {
    __shared__ int sums[1024];
    const int t = threadIdx.x;
    const int chunk = (n + 1023) / 1024;
    const int begin = t * chunk;
    const int end   = min(begin + chunk, n);
    int s = 0;
    for (int i = begin; i < end; i++) s += hist[i];
    sums[t] = s;
    __syncthreads();
    for (int d = 1; d < 1024; d <<= 1) {
        int v = (t >= d) ? sums[t - d] : 0;
        __syncthreads();
        sums[t] += v;
        __syncthreads();
    }
    int off = sums[t] - s;   // exclusive prefix
    for (int i = begin; i < end; i++) {
        rowptr[i] = off;
        woff[i]   = off;
        off += hist[i];
    }
    if (end == n && begin <= n) rowptr[n] = off;
}
__global__ void edge_bucket4(const int* __restrict__ src, const int* __restrict__ dst,
                             int* woff, int* ssrc, int E4) {
    int i = blockIdx.x * blockDim.x + threadIdx.x;
    if (i < E4) {
        int4 d = reinterpret_cast<const int4*>(dst)[i];
        int4 s = reinterpret_cast<const int4*>(src)[i];
        int p0 = atomicAdd(&woff[d.x], 1);
        int p1 = atomicAdd(&woff[d.y], 1);
        int p2 = atomicAdd(&woff[d.z], 1);
        int p3 = atomicAdd(&woff[d.w], 1);
        ssrc[p0] = s.x;
        ssrc[p1] = s.y;
        ssrc[p2] = s.z;
        ssrc[p3] = s.w;
    }
}

// ---------------- dual GEMM (FFMA2): C0 = act(A)@W0+b0 ; C1 = act(A)@W1+b1 --
// R6 config restored: TM=8, TN=4, BM=32, 3 CTAs/SM — best measured point.
template<int BN, int TM, int TN, int MAXB>
__global__ void __launch_bounds__(256, MAXB)
gemm_dual_k128(const float* __restrict__ A,
               const float* __restrict__ W0, const float* __restrict__ b0,
               const float* __restrict__ W1, const float* __restrict__ b1,
               float* __restrict__ C0, float* __restrict__ C1,
               int N, int relu_in)
{
    constexpr int K = 128, KC = 32;
    constexpr int TCOLS = (2 * BN) / TN;
    constexpr int TROWS = 256 / TCOLS;
    constexpr int BM = TROWS * TM;
    static_assert(TM % 4 == 0 && TN % 4 == 0, "vectorized tiling");

    __shared__ __align__(16) float As[KC][BM + 4];
    __shared__ __align__(16) float Wsm[KC][2 * BN];

    const int t  = threadIdx.x;
    const int tx = t % TCOLS;
    const int ty = t / TCOLS;
    const int rowBase = blockIdx.x * BM;

    unsigned long long acc2[TM / 2][TN];
    #pragma unroll
    for (int i = 0; i < TM / 2; i++)
        #pragma unroll
        for (int j = 0; j < TN; j++) acc2[i][j] = 0ull;

    for (int kc = 0; kc < K; kc += KC) {
        #pragma unroll
        for (int i = 0; i < (BM * KC) / (256 * 4); ++i) {
            int fi = t + i * 256;
            int r  = fi / (KC / 4);
            int c4 = fi % (KC / 4);
            int gr = rowBase + r;
            float4 v = make_float4(0.f, 0.f, 0.f, 0.f);
            if (gr < N) {
                v = reinterpret_cast<const float4*>(A + (size_t)gr * K + kc)[c4];
                if (relu_in) {
                    v.x = fmaxf(v.x, 0.f); v.y = fmaxf(v.y, 0.f);
                    v.z = fmaxf(v.z, 0.f); v.w = fmaxf(v.w, 0.f);
                }
            }
            As[c4 * 4 + 0][r] = v.x;
            As[c4 * 4 + 1][r] = v.y;
            As[c4 * 4 + 2][r] = v.z;
            As[c4 * 4 + 3][r] = v.w;
        }
        #pragma unroll
        for (int i = 0; i < (KC * 2 * BN) / (256 * 4); ++i) {
            int fi = t + i * 256;
            int r  = fi / ((2 * BN) / 4);
            int c4 = fi % ((2 * BN) / 4);
            int col = c4 * 4;
            float4 v;
            if (col < BN) v = reinterpret_cast<const float4*>(W0 + (size_t)(kc + r) * BN + col)[0];
            else          v = reinterpret_cast<const float4*>(W1 + (size_t)(kc + r) * BN + (col - BN))[0];
            reinterpret_cast<float4*>(&Wsm[r][0])[c4] = v;
        }
        __syncthreads();

        #pragma unroll
        for (int k = 0; k < KC; k++) {
            unsigned long long ap[TM / 2];
            #pragma unroll
            for (int i = 0; i < TM / 4; i++) {
                ulonglong2 q = *reinterpret_cast<const ulonglong2*>(&As[k][ty * TM + i * 4]);
                ap[i * 2 + 0] = q.x;
                ap[i * 2 + 1] = q.y;
            }
            unsigned long long wd[TN];
            #pragma unroll
            for (int j = 0; j < TN / 4; j++) {
                float4 w = *reinterpret_cast<const float4*>(&Wsm[k][tx * TN + j * 4]);
                wd[j * 4 + 0] = pack2(w.x, w.x);
                wd[j * 4 + 1] = pack2(w.y, w.y);
                wd[j * 4 + 2] = pack2(w.z, w.z);
                wd[j * 4 + 3] = pack2(w.w, w.w);
            }
            #pragma unroll
            for (int i = 0; i < TM / 2; i++)
                #pragma unroll
                for (int j = 0; j < TN; j++)
                    acc2[i][j] = fma2(ap[i], wd[j], acc2[i][j]);
        }
        __syncthreads();
    }

    const int half = (tx * TN) / BN;
    const int col  = (tx * TN) % BN;
    float*       C  = half ? C1 : C0;
    const float* bb = half ? b1 : b0;
    float bias[TN];
    #pragma unroll
    for (int j = 0; j < TN; j++) bias[j] = bb[col + j];

    #pragma unroll
    for (int i = 0; i < TM / 2; i++) {
        float lo[TN], hi[TN];
        #pragma unroll
        for (int j = 0; j < TN; j++) unpack2(acc2[i][j], lo[j], hi[j]);
        int gr0 = rowBase + ty * TM + 2 * i;
        int gr1 = gr0 + 1;
        if (gr0 < N) {
            #pragma unroll
            for (int j = 0; j < TN / 4; j++) {
                float4 o = make_float4(lo[j*4+0] + bias[j*4+0], lo[j*4+1] + bias[j*4+1],
                                       lo[j*4+2] + bias[j*4+2], lo[j*4+3] + bias[j*4+3]);
                *reinterpret_cast<float4*>(C + (size_t)gr0 * BN + col + j * 4) = o;
            }
        }
        if (gr1 < N) {
            #pragma unroll
            for (int j = 0; j < TN / 4; j++) {
                float4 o = make_float4(hi[j*4+0] + bias[j*4+0], hi[j*4+1] + bias[j*4+1],
                                       hi[j*4+2] + bias[j*4+2], hi[j*4+3] + bias[j*4+3]);
                *reinterpret_cast<float4*>(C + (size_t)gr1 * BN + col + j * 4) = o;
            }
        }
    }
}

// ========== CSR edge aggregation, H=4: warp/dst, batched indices + 2-edge ILP
// Indices for up to 32 edges are loaded with ONE coalesced LDG (lane i gets
// ssrc[base+i]) and distributed via SHFL.IDX — removing the dependent
// index-load -> gather L2 round-trip chain from the per-edge critical path.
__global__ void edge_csr4(const int* __restrict__ rowptr, const int* __restrict__ ssrc,
                          const float* __restrict__ fs, const float* __restrict__ fd,
                          const float* __restrict__ a, float* __restrict__ out, int N)
{
    const int lane = threadIdx.x & 31;
    const int d    = (blockIdx.x * blockDim.x + threadIdx.x) >> 5;
    if (d >= N) return;

    const float4* fs4 = reinterpret_cast<const float4*>(fs);
    float4 v  = reinterpret_cast<const float4*>(fd)[(size_t)d * 32 + lane];
    float4 av = reinterpret_cast<const float4*>(a)[lane];

    float4 acc = make_float4(0.f, 0.f, 0.f, 0.f);
    float den = 0.f;

    const int start = rowptr[d];
    const int end   = rowptr[d + 1];

    for (int base = start; base < end; base += 32) {
        const int cnt = min(32, end - base);
        const int mi  = base + lane;
        int sidx = (mi < end) ? __ldg(ssrc + mi) : 0;   // one coalesced load / chunk

        // prefetch first pair (indices clamped; phantom edges masked at exp)
        int c0 = 0, c1 = min(1, cnt - 1);
        float4 ua = fs4[(size_t)__shfl_sync(0xffffffffu, sidx, c0) * 32 + lane];
        float4 ub = fs4[(size_t)__shfl_sync(0xffffffffu, sidx, c1) * 32 + lane];

        for (int j = 0; j < cnt; j += 2) {
            float4 u0 = ua, u1 = ub;
            int n0 = min(j + 2, cnt - 1);
            int n1 = min(j + 3, cnt - 1);
            ua = fs4[(size_t)__shfl_sync(0xffffffffu, sidx, n0) * 32 + lane];
            ub = fs4[(size_t)__shfl_sync(0xffffffffu, sidx, n1) * 32 + lane];

            float p0 = lrelu(u0.x + v.x) * av.x + lrelu(u0.y + v.y) * av.y
                     + lrelu(u0.z + v.z) * av.z + lrelu(u0.w + v.w) * av.w;
            float p1 = lrelu(u1.x + v.x) * av.x + lrelu(u1.y + v.y) * av.y
                     + lrelu(u1.z + v.z) * av.z + lrelu(u1.w + v.w) * av.w;
            p0 += __shfl_xor_sync(0xffffffffu, p0, 1);
            p1 += __shfl_xor_sync(0xffffffffu, p1, 1);
            p0 += __shfl_xor_sync(0xffffffffu, p0, 2);
            p1 += __shfl_xor_sync(0xffffffffu, p1, 2);
            p0 += __shfl_xor_sync(0xffffffffu, p0, 4);
            p1 += __shfl_xor_sync(0xffffffffu, p1, 4);
            float ex0 = __expf(p0);                        // shift-invariant softmax
            float ex1 = (j + 1 < cnt) ? __expf(p1) : 0.f;  // mask phantom edge
            acc.x = fmaf(u0.x, ex0, acc.x);
            acc.y = fmaf(u0.y, ex0, acc.y);
            acc.z = fmaf(u0.z, ex0, acc.z);
            acc.w = fmaf(u0.w, ex0, acc.w);
            acc.x = fmaf(u1.x, ex1, acc.x);
            acc.y = fmaf(u1.y, ex1, acc.y);
            acc.z = fmaf(u1.z, ex1, acc.z);
            acc.w = fmaf(u1.w, ex1, acc.w);
            den += ex0 + ex1;
        }
    }
    float sc = (den > 0.f) ? 1.0f / den : 0.f;   // zero-degree -> zeros
    acc.x *= sc; acc.y *= sc; acc.z *= sc; acc.w *= sc;
    reinterpret_cast<float4*>(out)[(size_t)d * 32 + lane] = acc;
}

// ========== CSR edge aggregation, H=1 (32 feats): warp=dst, 4 edge slots ====
__global__ void edge_csr1(const int* __restrict__ rowptr, const int* __restrict__ ssrc,
                          const float* __restrict__ fs, const float* __restrict__ fd,
                          const float* __restrict__ a, float* __restrict__ out, int N)
{
    const int lane = threadIdx.x & 31;
    const int d    = (blockIdx.x * blockDim.x + threadIdx.x) >> 5;
    if (d >= N) return;
    const int slot = lane >> 3;
    const int sub  = lane & 7;

    const float4* fs4 = reinterpret_cast<const float4*>(fs);
    float4 v  = reinterpret_cast<const float4*>(fd)[(size_t)d * 8 + sub];
    float4 av = reinterpret_cast<const float4*>(a)[sub];

    float4 acc = make_float4(0.f, 0.f, 0.f, 0.f);
    float den = 0.f;

    const int start = rowptr[d];
    const int end   = rowptr[d + 1];
    const int iters = (end - start + 3) >> 2;

    int idx0 = start + slot;
    float4 un = make_float4(0.f, 0.f, 0.f, 0.f);
    if (idx0 < end) un = fs4[(size_t)__ldg(ssrc + idx0) * 8 + sub];

    for (int it = 0; it < iters; it++) {
        bool ok = (start + it * 4 + slot) < end;
        float4 u = un;
        int nidx = start + (it + 1) * 4 + slot;
        if (nidx < end) un = fs4[(size_t)__ldg(ssrc + nidx) * 8 + sub];
        else            un = make_float4(0.f, 0.f, 0.f, 0.f);

        float p = lrelu(u.x + v.x) * av.x + lrelu(u.y + v.y) * av.y
                + lrelu(u.z + v.z) * av.z + lrelu(u.w + v.w) * av.w;
        p += __shfl_xor_sync(0xffffffffu, p, 1);
        p += __shfl_xor_sync(0xffffffffu, p, 2);
        p += __shfl_xor_sync(0xffffffffu, p, 4);
        float ex = ok ? __expf(p) : 0.f;
        acc.x = fmaf(u.x, ex, acc.x);
        acc.y = fmaf(u.y, ex, acc.y);
        acc.z = fmaf(u.z, ex, acc.z);
        acc.w = fmaf(u.w, ex, acc.w);
        den += ex;
    }
    #pragma unroll
    for (int m = 8; m <= 16; m <<= 1) {
        acc.x += __shfl_xor_sync(0xffffffffu, acc.x, m);
        acc.y += __shfl_xor_sync(0xffffffffu, acc.y, m);
        acc.z += __shfl_xor_sync(0xffffffffu, acc.z, m);
        acc.w += __shfl_xor_sync(0xffffffffu, acc.w, m);
        den   += __shfl_xor_sync(0xffffffffu, den,   m);
    }
    if (slot == 0) {
        float sc = (den > 0.f) ? 1.0f / den : 0.f;
        acc.x *= sc; acc.y *= sc; acc.z *= sc; acc.w *= sc;
        reinterpret_cast<float4*>(out)[(size_t)d * 8 + sub] = acc;
    }
}

// ---------------- launch -----------------------------------------------------
extern "C" void kernel_launch(void* const* d_in, const int* in_sizes, int n_in,
                              void* d_out, int out_size)
{
    const float* feat = (const float*)d_in[0];
    const int*   src  = (const int*)d_in[1];
    const int*   dst  = (const int*)d_in[2];
    const float* Ws0 = (const float*)d_in[3];  const float* bs0 = (const float*)d_in[4];
    const float* Wd0 = (const float*)d_in[5];  const float* bd0 = (const float*)d_in[6];
    const float* a0  = (const float*)d_in[7];
    const float* Ws1 = (const float*)d_in[8];  const float* bs1 = (const float*)d_in[9];
    const float* Wd1 = (const float*)d_in[10]; const float* bd1 = (const float*)d_in[11];
    const float* a1  = (const float*)d_in[12];
    const float* Ws2 = (const float*)d_in[13]; const float* bs2 = (const float*)d_in[14];
    const float* Wd2 = (const float*)d_in[15]; const float* bd2 = (const float*)d_in[16];
    const float* a2  = (const float*)d_in[17];
    float* out = (float*)d_out;

    const int N = in_sizes[0] / 128;
    const int E = in_sizes[1];

    float *fs, *fd, *h;
    int *hist, *rowptr, *woff, *ssrc;
    cudaGetSymbolAddress((void**)&fs,     g_fs);
    cudaGetSymbolAddress((void**)&fd,     g_fd);
    cudaGetSymbolAddress((void**)&h,      g_h);
    cudaGetSymbolAddress((void**)&hist,   g_hist);
    cudaGetSymbolAddress((void**)&rowptr, g_rowptr);
    cudaGetSymbolAddress((void**)&woff,   g_woff);
    cudaGetSymbolAddress((void**)&ssrc,   g_ssrc);

    const int gemmGridBig   = (N + 31) / 32;   // BM=32 (TM=8, TN=4, 3 CTAs)
    const int gemmGridSmall = (N + 63) / 64;   // BM=64 (TM=4, TN=4)
    const int edgeGrid = (N * 32 + 255) / 256; // one warp per dst
    const int E4 = E / 4;
    const int eg4 = (E4 + 255) / 256;

    // ---- CSR build (src/dst constant across layers; reused 3x) ----
    cudaMemsetAsync(hist, 0, (size_t)N * sizeof(int));
    hist_count4<<<eg4, 256>>>(dst, hist, E4);
    scan_hist<<<1, 1024>>>(hist, rowptr, woff, N);
    edge_bucket4<<<eg4, 256>>>(src, dst, woff, ssrc, E4);

    // ---- layer 0 (input 128 -> 4x32) ----
    gemm_dual_k128<128, 8, 4, 3><<<gemmGridBig, 256>>>(feat, Ws0, bs0, Wd0, bd0, fs, fd, N, 0);
    edge_csr4<<<edgeGrid, 256>>>(rowptr, ssrc, fs, fd, a0, h, N);

    // ---- layer 1 (ReLU(h) 128 -> 4x32) ----
    gemm_dual_k128<128, 8, 4, 3><<<gemmGridBig, 256>>>(h, Ws1, bs1, Wd1, bd1, fs, fd, N, 1);
    edge_csr4<<<edgeGrid, 256>>>(rowptr, ssrc, fs, fd, a1, h, N);

    // ---- layer 2 (ReLU(h) 128 -> 1x32), mean over 1 head == identity ----
    gemm_dual_k128<32, 4, 4, 2><<<gemmGridSmall, 256>>>(h, Ws2, bs2, Wd2, bd2, fs, fd, N, 1);
    edge_csr1<<<edgeGrid, 256>>>(rowptr, ssrc, fs, fd, a2, out, N);
}